// round 16
// baseline (speedup 1.0000x reference)
#include <cuda_runtime.h>
#include <cuda_fp16.h>

// RankDPO loss, B=8192, K=64. Single fused kernel.
// R16: exp-sum softplus — softplus_lg2(sLi - sLj) = lg2(Ei + Ej) - sLj with
// E = 2^sL precomputed per ELEMENT (2 EX2 total/thread). Each pair costs ONE
// LG2 and ZERO EX2; the -sLj terms collapse into sL0*sumDtA + sL1*sumDtB
// (running FADD sums) plus the usual wrap correction (- sum dtB*xB).
// delta in half2 (values only; R15 precedent 2e-4). Rank compares EXACT f32.

#define ROWS_PER_BLOCK 8
#define THREADS 256
#define NUM_BLOCKS 1024                      // 8192 / 8
#define LOG2E 1.4426950408889634f
#define LN2   0.6931471805599453f
#define FINAL_SCALE (LN2 / 16515072.0f)      // ln2 / (8192 * 2016)

static __device__ float g_partials[NUM_BLOCKS];
static __device__ unsigned int g_ticket = 0;

typedef unsigned long long u64;

static __device__ __forceinline__ float ex2f(float x) {
    float y; asm("ex2.approx.f32 %0, %1;" : "=f"(y) : "f"(x)); return y;
}
static __device__ __forceinline__ float lg2f(float x) {
    float y; asm("lg2.approx.f32 %0, %1;" : "=f"(y) : "f"(x)); return y;
}
static __device__ __forceinline__ u64 packf2(float lo, float hi) {
    u64 r; asm("mov.b64 %0, {%1, %2};" : "=l"(r) : "f"(lo), "f"(hi)); return r;
}
static __device__ __forceinline__ void unpackf2(float& lo, float& hi, u64 v) {
    asm("mov.b64 {%0, %1}, %2;" : "=f"(lo), "=f"(hi) : "l"(v));
}
static __device__ __forceinline__ u64 addx2(u64 a, u64 b) {
    u64 r; asm("add.rn.f32x2 %0, %1, %2;" : "=l"(r) : "l"(a), "l"(b)); return r;
}
static __device__ __forceinline__ float h2f(__half2 h) {
    unsigned u; __builtin_memcpy(&u, &h, 4); return __uint_as_float(u);
}
static __device__ __forceinline__ __half2 f2h2(float f) {
    unsigned u = __float_as_uint(f); __half2 h; __builtin_memcpy(&h, &u, 4); return h;
}

__global__ __launch_bounds__(THREADS, 7)
void rankdpo_fused(const float* __restrict__ S,
                   const float* __restrict__ R,
                   float* __restrict__ out) {
    __shared__ __align__(16) float4 Etab[ROWS_PER_BLOCK][64];  // {E, E', sL, sL'}
    __shared__ __align__(8)  float2 Gtab[ROWS_PER_BLOCK][64];  // {h2(g,g'), h2(d,d')}
    __shared__ __align__(16) float  rsh[ROWS_PER_BLOCK][64];
    __shared__ float wsum[ROWS_PER_BLOCK];
    __shared__ float red[THREADS];
    __shared__ int   isLast;

    const int warp = threadIdx.x >> 5;
    const int lane = threadIdx.x & 31;
    const int row  = blockIdx.x * ROWS_PER_BLOCK + warp;

    const float* srow = S + row * 64;
    const float* rrow = R + row * 64;
    const float s0 = srow[lane];
    const float s1 = srow[lane + 32];
    const float r0 = rrow[lane];
    const float r1 = rrow[lane + 32];

    float* rw = rsh[warp];
    rw[lane]      = r0;
    rw[lane + 32] = r1;
    __syncwarp();

    // ---- rank: EXACT f32 strictly-greater counts ----
    int c0 = 0, c1 = 0;
    const float4* rv = (const float4*)rw;
    #pragma unroll
    for (int q = 0; q < 16; q++) {
        const float4 v = rv[q];
        c0 += (v.x > r0) + (v.y > r0) + (v.z > r0) + (v.w > r0);
        c1 += (v.x > r1) + (v.y > r1) + (v.z > r1) + (v.w > r1);
    }
    const float d0 = __fdividef(1.f, __logf((float)(c0 + 2)));
    const float d1 = __fdividef(1.f, __logf((float)(c1 + 2)));
    const float g0 = 2.f * r0 - 1.f;
    const float g1 = 2.f * r1 - 1.f;
    const float sL0 = s0 * LOG2E;          // lg2-domain score
    const float sL1 = s1 * LOG2E;
    const float E0  = ex2f(sL0);           // 2^sL, once per element
    const float E1  = ex2f(sL1);

    // interleaved tables: entry m serves pair (m,.) and the (m+32)-side pair
    const __half2 gd01 = __floats2half2_rn(g0, g1);
    const __half2 dd01 = __floats2half2_rn(d0, d1);
    const __half2 gd10 = __lowhigh2highlow(gd01);
    const __half2 dd10 = __lowhigh2highlow(dd01);
    Etab[warp][lane]      = make_float4(E0, E1, sL0, sL1);
    Etab[warp][lane + 32] = make_float4(E1, E0, sL1, sL0);
    Gtab[warp][lane]      = make_float2(h2f(gd01), h2f(dd01));
    Gtab[warp][lane + 32] = make_float2(h2f(gd10), h2f(dd10));
    __syncwarp();

    const u64 E2own = packf2(E0, E1);
    const __half2 gOwn = gd01;   // {g0, g1}
    const __half2 dOwn = dd01;   // {d0, d1}

    const float4* Eb = &Etab[warp][lane];
    const float2* Gb = &Gtab[warp][lane];

    float accL0 = 0.f, accL1 = 0.f;    // sum delta * lg2(E_own + E_partner)
    float sumA = 0.f, sumB = 0.f;      // sum delta (for the -sL_own terms)
    float accC = 0.f;                  // wrap correction: sum dtB * xB
    #pragma unroll
    for (int k = 1; k < 32; k++) {
        const float4 A = Eb[k];        // {E_m, E_m', sL_m, sL_m'}
        const float2 G = Gb[k];        // {h2(g_m,g_m'), h2(d_m,d_m')}

        // packed E sums: {E0+E_m, E1+E_m'} ((A.x,A.y) is an aligned reg pair)
        const u64 es2 = addx2(packf2(A.x, A.y), E2own);
        float eA, eB;
        unpackf2(eA, eB, es2);

        // delta in half2, both pairs at once (>= 0 by monotonicity)
        const __half2 pr = __hmul2(__hsub2(f2h2(G.x), gOwn),
                                   __hsub2(f2h2(G.y), dOwn));
        const float dtA = __low2float(pr);
        const float dtB = __high2float(pr);

        // ONE lg2 per pair, NO ex2
        accL0 = fmaf(dtA, lg2f(eA), accL0);
        accL1 = fmaf(dtB, lg2f(eB), accL1);
        sumA += dtA;
        sumB += dtB;

        // pair B wrapped (lane+k>=32): oriented subtracts sL_partner instead
        // of sL1 -> correct by -dtB*(sL_partner - sL1)
        if (lane + k >= 32) accC = fmaf(dtB, A.w - sL1, accC);
    }
    {   // gap-32 pair (lane, lane+32): i = lane+32 > j = lane — exact f32
        const float delta = (g1 - g0) * (d1 - d0);   // >= 0
        accL0 = fmaf(delta, lg2f(E0 + E1), accL0);
        sumA += delta;                                // subtract sL0 (j = lane)
    }
    // total (lg2 domain): sum delta*lg2(Ei+Ej) - sL_j terms - wrap correction
    float acc = accL0 + accL1 - sL0 * sumA - sL1 * sumB - accC;

    // ---- warp reduce ----
    #pragma unroll
    for (int o = 16; o; o >>= 1)
        acc += __shfl_xor_sync(0xffffffffu, acc, o);
    if (lane == 0) wsum[warp] = acc;
    __syncthreads();

    if (threadIdx.x == 0) {
        float s = 0.f;
        #pragma unroll
        for (int w = 0; w < ROWS_PER_BLOCK; w++) s += wsum[w];
        g_partials[blockIdx.x] = s;
        __threadfence();
        const unsigned tk = atomicAdd(&g_ticket, 1u);
        isLast = (tk == (unsigned)(gridDim.x - 1));
    }
    __syncthreads();

    // ---- last block: deterministic fixed-order reduction of 1024 partials ----
    if (isLast) {
        const int tid = threadIdx.x;
        float v = g_partials[tid]
                + g_partials[tid + 256]
                + g_partials[tid + 512]
                + g_partials[tid + 768];
        red[tid] = v;
        __syncthreads();
        #pragma unroll
        for (int stride = THREADS / 2; stride > 0; stride >>= 1) {
            if (tid < stride) red[tid] += red[tid + stride];
            __syncthreads();
        }
        if (tid == 0) {
            out[0] = red[0] * FINAL_SCALE;
            g_ticket = 0;   // reset for graph replay
        }
    }
}

extern "C" void kernel_launch(void* const* d_in, const int* in_sizes, int n_in,
                              void* d_out, int out_size) {
    (void)in_sizes; (void)n_in; (void)out_size;
    const float* s = (const float*)d_in[0];   // policy_logps
    const float* r = (const float*)d_in[1];   // reward_scores
    rankdpo_fused<<<NUM_BLOCKS, THREADS>>>(s, r, (float*)d_out);
}

// round 17
// speedup vs baseline: 1.1212x; 1.1212x over previous
#include <cuda_runtime.h>
#include <cuda_fp16.h>

// RankDPO loss, B=8192, K=64. Single fused kernel.
// R17 = R15 pair loop (best: ONE LDS.128/iter, half2 delta) + fast epilogue:
// shuffle-based reductions, single __syncthreads in the final tree.
//   P[m] = {sL[m], sL[m'], half2(g[m],g[m']), half2(d[m],d[m'])}, m'=(m+32)&63
// Rank compares EXACT f32 (R12 lesson). delta >= 0 by monotonicity (no abs).
// softplus in lg2 domain; wrapped pair-B via correction accumulator
// (softplus(-x) = softplus(x) - x).

#define ROWS_PER_BLOCK 8
#define THREADS 256
#define NUM_BLOCKS 1024                      // 8192 / 8
#define LOG2E 1.4426950408889634f
#define LN2   0.6931471805599453f
#define FINAL_SCALE (LN2 / 16515072.0f)      // ln2 / (8192 * 2016)

static __device__ float g_partials[NUM_BLOCKS];
static __device__ unsigned int g_ticket = 0;

typedef unsigned long long u64;

static __device__ __forceinline__ float ex2f(float x) {
    float y; asm("ex2.approx.f32 %0, %1;" : "=f"(y) : "f"(x)); return y;
}
static __device__ __forceinline__ float lg2f(float x) {
    float y; asm("lg2.approx.f32 %0, %1;" : "=f"(y) : "f"(x)); return y;
}
static __device__ __forceinline__ u64 packf2(float lo, float hi) {
    u64 r; asm("mov.b64 %0, {%1, %2};" : "=l"(r) : "f"(lo), "f"(hi)); return r;
}
static __device__ __forceinline__ void unpackf2(float& lo, float& hi, u64 v) {
    asm("mov.b64 {%0, %1}, %2;" : "=f"(lo), "=f"(hi) : "l"(v));
}
static __device__ __forceinline__ u64 addx2(u64 a, u64 b) {
    u64 r; asm("add.rn.f32x2 %0, %1, %2;" : "=l"(r) : "l"(a), "l"(b)); return r;
}
static __device__ __forceinline__ float h2f(__half2 h) {
    unsigned u; __builtin_memcpy(&u, &h, 4); return __uint_as_float(u);
}
static __device__ __forceinline__ __half2 f2h2(float f) {
    unsigned u = __float_as_uint(f); __half2 h; __builtin_memcpy(&h, &u, 4); return h;
}

__global__ __launch_bounds__(THREADS, 7)
void rankdpo_fused(const float* __restrict__ S,
                   const float* __restrict__ R,
                   float* __restrict__ out) {
    __shared__ __align__(16) float4 Ptab[ROWS_PER_BLOCK][64];
    __shared__ __align__(16) float  rsh[ROWS_PER_BLOCK][64];
    __shared__ float wsum[ROWS_PER_BLOCK];
    __shared__ float rsum[8];
    __shared__ int   isLast;

    const int warp = threadIdx.x >> 5;
    const int lane = threadIdx.x & 31;
    const int row  = blockIdx.x * ROWS_PER_BLOCK + warp;

    const float* srow = S + row * 64;
    const float* rrow = R + row * 64;
    const float s0 = srow[lane];
    const float s1 = srow[lane + 32];
    const float r0 = rrow[lane];
    const float r1 = rrow[lane + 32];

    float* rw = rsh[warp];
    rw[lane]      = r0;
    rw[lane + 32] = r1;
    __syncwarp();

    // ---- rank: EXACT f32 strictly-greater counts (ties ~2^-23/pair; tied
    //      pairs have dg=0 -> delta=0, so the dropped tie-break is harmless) --
    int c0 = 0, c1 = 0;
    const float4* rv = (const float4*)rw;
    #pragma unroll
    for (int q = 0; q < 16; q++) {
        const float4 v = rv[q];
        c0 += (v.x > r0) + (v.y > r0) + (v.z > r0) + (v.w > r0);
        c1 += (v.x > r1) + (v.y > r1) + (v.z > r1) + (v.w > r1);
    }
    const float d0 = __fdividef(1.f, __logf((float)(c0 + 2)));
    const float d1 = __fdividef(1.f, __logf((float)(c1 + 2)));
    const float g0 = 2.f * r0 - 1.f;
    const float g1 = 2.f * r1 - 1.f;
    const float sL0 = s0 * LOG2E;   // lg2-domain score
    const float sL1 = s1 * LOG2E;

    // single merged table: one 16B record per entry -> ONE LDS.128 per iter
    const __half2 gd01 = __floats2half2_rn(g0, g1);
    const __half2 dd01 = __floats2half2_rn(d0, d1);
    const __half2 gd10 = __lowhigh2highlow(gd01);
    const __half2 dd10 = __lowhigh2highlow(dd01);
    Ptab[warp][lane]      = make_float4(sL0, sL1, h2f(gd01), h2f(dd01));
    Ptab[warp][lane + 32] = make_float4(sL1, sL0, h2f(gd10), h2f(dd10));
    __syncwarp();

    const u64 negS2 = packf2(-sL0, -sL1);
    const __half2 gOwn = gd01;   // {g0, g1}
    const __half2 dOwn = dd01;   // {d0, d1}

    const float4* Pb = &Ptab[warp][lane];

    float acc0 = 0.f;   // pair-A softplus_lg2 terms
    float acc1 = 0.f;   // pair-B unoriented softplus_lg2 terms
    float accC = 0.f;   // pair-B wrapped correction: sum delta*x (lg2 domain)
    #pragma unroll
    for (int k = 1; k < 32; k++) {
        const float4 A = Pb[k];   // ONE LDS.128: {sL[m], sL[m'], h2(g), h2(d)}

        // packed producer on the naturally-aligned (A.x, A.y) register pair
        const u64 x2 = addx2(packf2(A.x, A.y), negS2);
        float xA, xB;
        unpackf2(xA, xB, x2);

        // delta in half2: (g_m - g_own) * (d_m - d_own), both lanes at once
        const __half2 pr = __hmul2(__hsub2(f2h2(A.z), gOwn),
                                   __hsub2(f2h2(A.w), dOwn));
        const float dtA = __low2float(pr);
        const float dtB = __high2float(pr);

        // pair A: partner index lane+k > lane always -> oriented as-is
        acc0 = fmaf(dtA, lg2f(1.f + ex2f(xA)), acc0);

        // pair B: unoriented softplus; wrapped (lane+k>=32 -> partner < own):
        // oriented value = lB - xB, folded via correction accumulator
        acc1 = fmaf(dtB, lg2f(1.f + ex2f(xB)), acc1);
        if (lane + k >= 32) accC = fmaf(dtB, xB, accC);
    }
    {   // gap-32 pair (lane, lane+32): i = lane+32 > j = lane — exact f32
        const float delta = (g1 - g0) * (d1 - d0);   // >= 0
        acc0 = fmaf(delta, lg2f(1.f + ex2f(sL1 - sL0)), acc0);
    }
    float acc = acc0 + acc1 - accC;   // lg2 domain; ln2 folded into FINAL_SCALE

    // ---- warp reduce ----
    #pragma unroll
    for (int o = 16; o; o >>= 1)
        acc += __shfl_xor_sync(0xffffffffu, acc, o);
    if (lane == 0) wsum[warp] = acc;
    __syncthreads();

    // ---- block sum: lane-parallel (warp 0 reads all 8, shuffle over 8) ----
    if (warp == 0) {
        float b = (lane < ROWS_PER_BLOCK) ? wsum[lane] : 0.f;
        #pragma unroll
        for (int o = 4; o; o >>= 1)
            b += __shfl_xor_sync(0xffffffffu, b, o);
        if (lane == 0) {
            g_partials[blockIdx.x] = b;
            __threadfence();
            const unsigned tk = atomicAdd(&g_ticket, 1u);
            isLast = (tk == (unsigned)(gridDim.x - 1));
        }
    }
    __syncthreads();

    // ---- last block: deterministic shuffle reduction of 1024 partials ----
    if (isLast) {
        const int tid = threadIdx.x;
        // 4 parallel LDGs per thread, fixed order
        float v = g_partials[tid]
                + g_partials[tid + 256]
                + g_partials[tid + 512]
                + g_partials[tid + 768];
        #pragma unroll
        for (int o = 16; o; o >>= 1)
            v += __shfl_xor_sync(0xffffffffu, v, o);
        if (lane == 0) rsum[warp] = v;
        __syncthreads();
        if (warp == 0) {
            float x = (lane < 8) ? rsum[lane] : 0.f;
            #pragma unroll
            for (int o = 4; o; o >>= 1)
                x += __shfl_xor_sync(0xffffffffu, x, o);
            if (lane == 0) {
                out[0] = x * FINAL_SCALE;
                g_ticket = 0;   // reset for graph replay
            }
        }
    }
}

extern "C" void kernel_launch(void* const* d_in, const int* in_sizes, int n_in,
                              void* d_out, int out_size) {
    (void)in_sizes; (void)n_in; (void)out_size;
    const float* s = (const float*)d_in[0];   // policy_logps
    const float* r = (const float*)d_in[1];   // reward_scores
    rankdpo_fused<<<NUM_BLOCKS, THREADS>>>(s, r, (float*)d_out);
}